// round 1
// baseline (speedup 1.0000x reference)
#include <cuda_runtime.h>
#include <math.h>

#define T_STEPS 1024
#define HID     256
#define G4      1024
#define NSPK    1251
#define F_IN    40

// ---------------- device scratch (no allocation allowed) ----------------
__device__ float g_xg[3][T_STEPS][G4];   // per-layer input projections (+biases)
__device__ float g_h [3][T_STEPS][HID];  // per-layer hidden outputs
__device__ int   g_fxg[3][T_STEPS][8];   // flags: projection ready (8 producer CTAs)
__device__ int   g_fh [3][T_STEPS][16];  // flags: h slice ready (16 producer CTAs)

// ---------------- acquire/release helpers ----------------
__device__ __forceinline__ int ld_acq(const int* p) {
    int v;
    asm volatile("ld.global.acquire.gpu.b32 %0, [%1];" : "=r"(v) : "l"(p));
    return v;
}
__device__ __forceinline__ void st_rel(int* p, int v) {
    asm volatile("st.global.release.gpu.b32 [%0], %1;" :: "l"(p), "r"(v));
}

__device__ __forceinline__ float sigmoidf_(float x) {
    return 1.0f / (1.0f + __expf(-x));
}

// ---------------- init: zero all flags (must run every launch) ----------------
__global__ void init_flags_kernel() {
    int i = blockIdx.x * blockDim.x + threadIdx.x;
    int* f1 = &g_fxg[0][0][0];           // 3*1024*8  = 24576
    int* f2 = &g_fh[0][0][0];            // 3*1024*16 = 49152
    if (i < 24576) f1[i] = 0;
    if (i < 49152) f2[i] = 0;
}

// ---------------- main persistent pipeline kernel ----------------
// grid = 72 blocks x 512 threads (all co-resident on 148 SMs)
//  blocks  0..47 : recurrent stages L0/L1/L2 (16 CTAs each)
//  blocks 48..55 : P0 (xg for layer0 from x[63])
//  blocks 56..63 : P1 (xg for layer1 from h0)
//  blocks 64..71 : P2 (xg for layer2 from h1)
__global__ __launch_bounds__(512, 1) void lstm_pipeline_kernel(
    const float* __restrict__ x,
    const float* __restrict__ wih0, const float* __restrict__ whh0,
    const float* __restrict__ bih0, const float* __restrict__ bhh0,
    const float* __restrict__ wih1, const float* __restrict__ whh1,
    const float* __restrict__ bih1, const float* __restrict__ bhh1,
    const float* __restrict__ wih2, const float* __restrict__ whh2,
    const float* __restrict__ bih2, const float* __restrict__ bhh2)
{
    __shared__ float h_s[HID];
    __shared__ float red[512];
    __shared__ float gbuf[64];
    __shared__ float bias_s[128];
    __shared__ float x_s[F_IN];

    const int bid = blockIdx.x;
    const int tid = threadIdx.x;

    if (bid < 48) {
        // ================= recurrent stage =================
        const int l = bid >> 4;          // layer 0..2
        const int c = bid & 15;          // CTA within layer, owns hidden units [c*16, c*16+16)
        const float* whh = (l == 0) ? whh0 : (l == 1) ? whh1 : whh2;

        const int r  = tid & 63;         // 0..63 : which of this CTA's 64 gate rows
        const int kc = tid >> 6;         // 0..7  : k-chunk of 32
        const int gate = r >> 4;         // 0..3 (i,f,g,o)
        const int ul   = r & 15;         // local hidden unit
        const int grow = gate * 256 + c * 16 + ul;   // global gate row in [0,1024)

        // W_hh slice in registers: 32 fp32 per thread
        float w[32];
        #pragma unroll
        for (int k = 0; k < 32; k++) w[k] = whh[grow * HID + kc * 32 + k];

        if (tid < HID) h_s[tid] = 0.0f;
        float cst = 0.0f;                // cell state (valid for tid<16)
        __syncthreads();

        for (int t = 0; t < T_STEPS; t++) {
            // partial matvec against h_{t-1} (broadcast smem reads)
            float p = 0.0f;
            #pragma unroll
            for (int k = 0; k < 32; k++) p = fmaf(w[k], h_s[kc * 32 + k], p);
            red[tid] = p;

            // overlap: poll projection flags while matvec partials drain
            if (tid >= 504) {
                while (ld_acq(&g_fxg[l][t][tid - 504]) == 0) {}
            }
            __syncthreads();

            if (tid < 64) {
                float s = red[tid];
                #pragma unroll
                for (int q = 1; q < 8; q++) s += red[q * 64 + tid];
                s += g_xg[l][t][grow];   // tid<64 => kc==0, r==tid, grow valid
                gbuf[tid] = s;
            }
            __syncthreads();

            if (tid < 16) {
                float gi = gbuf[tid];
                float gf = gbuf[16 + tid];
                float gc = gbuf[32 + tid];
                float go = gbuf[48 + tid];
                float ii = sigmoidf_(gi);
                float ff = sigmoidf_(gf);
                float cc = tanhf(gc);
                float oo = sigmoidf_(go);
                cst = ff * cst + ii * cc;
                float hn = oo * tanhf(cst);
                g_h[l][t][c * 16 + tid] = hn;
            }
            __syncthreads();
            if (tid == 0) { __threadfence(); st_rel(&g_fh[l][t][c], 1); }

            // gather full h_t from all 16 CTAs of this layer
            if (tid < 16) {
                while (ld_acq(&g_fh[l][t][tid]) == 0) {}
            }
            __syncthreads();
            if (tid < HID) h_s[tid] = g_h[l][t][tid];
            __syncthreads();
        }
    } else if (bid < 56) {
        // ================= P0: xg0[t] = W_ih0 @ x[63,t] + b =================
        const int p  = bid - 48;
        const int r  = tid & 127;        // row within this CTA's 128 rows
        const int kc = tid >> 7;         // 0..3, 10 input dims each
        const int grow = p * 128 + r;

        float w[10];
        #pragma unroll
        for (int k = 0; k < 10; k++) w[k] = wih0[grow * F_IN + kc * 10 + k];
        if (tid < 128) bias_s[tid] = bih0[p * 128 + tid] + bhh0[p * 128 + tid];
        __syncthreads();

        for (int t = 0; t < T_STEPS; t++) {
            if (tid < F_IN) x_s[tid] = x[(63 * T_STEPS + t) * F_IN + tid];
            __syncthreads();
            float pa = 0.0f;
            #pragma unroll
            for (int k = 0; k < 10; k++) pa = fmaf(w[k], x_s[kc * 10 + k], pa);
            red[tid] = pa;
            __syncthreads();
            if (tid < 128) {
                float s = red[tid] + red[128 + tid] + red[256 + tid] + red[384 + tid]
                        + bias_s[tid];
                g_xg[0][t][grow] = s;
            }
            __syncthreads();
            if (tid == 0) { __threadfence(); st_rel(&g_fxg[0][t][p], 1); }
        }
    } else {
        // ================= P1/P2: xg_l[t] = W_ih_l @ h_{l-1}[t] + b =================
        const int pl = bid - 56;
        const int l  = 1 + (pl >> 3);    // 1 or 2
        const int p  = pl & 7;
        const float* wih = (l == 1) ? wih1 : wih2;
        const float* bih = (l == 1) ? bih1 : bih2;
        const float* bhh = (l == 1) ? bhh1 : bhh2;

        const int r  = tid & 127;
        const int kc = tid >> 7;         // 0..3, 64 k each
        const int grow = p * 128 + r;

        float w[64];
        #pragma unroll
        for (int k = 0; k < 64; k++) w[k] = wih[grow * HID + kc * 64 + k];
        if (tid < 128) bias_s[tid] = bih[p * 128 + tid] + bhh[p * 128 + tid];
        __syncthreads();

        for (int t = 0; t < T_STEPS; t++) {
            if (tid < 16) {
                while (ld_acq(&g_fh[l - 1][t][tid]) == 0) {}
            }
            __syncthreads();
            if (tid < HID) h_s[tid] = g_h[l - 1][t][tid];
            __syncthreads();
            float pa = 0.0f;
            #pragma unroll
            for (int k = 0; k < 64; k++) pa = fmaf(w[k], h_s[kc * 64 + k], pa);
            red[tid] = pa;
            __syncthreads();
            if (tid < 128) {
                g_xg[l][t][grow] = red[tid] + red[128 + tid] + red[256 + tid]
                                 + red[384 + tid] + bias_s[tid];
            }
            __syncthreads();
            if (tid == 0) { __threadfence(); st_rel(&g_fxg[l][t][p], 1); }
        }
    }
}

// ---------------- classifier: logits = h2 @ W_lin^T + b, log_softmax ----------------
// grid = 256 blocks (4 timesteps each) x 512 threads
__global__ __launch_bounds__(512, 1) void classifier_kernel(
    const float* __restrict__ wlin,
    const float* __restrict__ blin,
    float* __restrict__ out)
{
    __shared__ float lg[4 * NSPK];       // ~20 KB
    __shared__ float hsm[4 * HID];       // 4 KB
    __shared__ float rbuf[16];

    const int b   = blockIdx.x;
    const int t0  = b * 4;
    const int tid = threadIdx.x;
    const int lane = tid & 31;
    const int wd   = tid >> 5;           // 0..15

    for (int i = tid; i < 4 * HID; i += 512)
        hsm[i] = g_h[2][t0 + (i >> 8)][i & 255];
    __syncthreads();

    // each lane caches its 8 h values per timestep in registers
    float hr[4][8];
    #pragma unroll
    for (int t = 0; t < 4; t++)
        #pragma unroll
        for (int j = 0; j < 8; j++) hr[t][j] = hsm[t * HID + lane * 8 + j];

    for (int o = wd; o < NSPK; o += 16) {
        const float4* wp = (const float4*)(wlin + o * HID + lane * 8);
        float4 w0 = wp[0], w1 = wp[1];
        float wv[8] = {w0.x, w0.y, w0.z, w0.w, w1.x, w1.y, w1.z, w1.w};
        float a0 = 0.f, a1 = 0.f, a2 = 0.f, a3 = 0.f;
        #pragma unroll
        for (int j = 0; j < 8; j++) {
            float wj = wv[j];
            a0 = fmaf(wj, hr[0][j], a0);
            a1 = fmaf(wj, hr[1][j], a1);
            a2 = fmaf(wj, hr[2][j], a2);
            a3 = fmaf(wj, hr[3][j], a3);
        }
        #pragma unroll
        for (int off = 16; off > 0; off >>= 1) {
            a0 += __shfl_xor_sync(0xffffffffu, a0, off);
            a1 += __shfl_xor_sync(0xffffffffu, a1, off);
            a2 += __shfl_xor_sync(0xffffffffu, a2, off);
            a3 += __shfl_xor_sync(0xffffffffu, a3, off);
        }
        if (lane == 0) {
            float bb = blin[o];
            lg[0 * NSPK + o] = a0 + bb;
            lg[1 * NSPK + o] = a1 + bb;
            lg[2 * NSPK + o] = a2 + bb;
            lg[3 * NSPK + o] = a3 + bb;
        }
    }
    __syncthreads();

    // log_softmax per timestep (axis = class dim)
    for (int t = 0; t < 4; t++) {
        float m = -1e30f;
        for (int o = tid; o < NSPK; o += 512) m = fmaxf(m, lg[t * NSPK + o]);
        #pragma unroll
        for (int off = 16; off > 0; off >>= 1)
            m = fmaxf(m, __shfl_xor_sync(0xffffffffu, m, off));
        if (lane == 0) rbuf[wd] = m;
        __syncthreads();
        float mm = rbuf[0];
        #pragma unroll
        for (int i = 1; i < 16; i++) mm = fmaxf(mm, rbuf[i]);
        __syncthreads();

        float s = 0.0f;
        for (int o = tid; o < NSPK; o += 512) s += __expf(lg[t * NSPK + o] - mm);
        #pragma unroll
        for (int off = 16; off > 0; off >>= 1)
            s += __shfl_xor_sync(0xffffffffu, s, off);
        if (lane == 0) rbuf[wd] = s;
        __syncthreads();
        float ss = 0.0f;
        #pragma unroll
        for (int i = 0; i < 16; i++) ss += rbuf[i];
        float lse = mm + logf(ss);

        for (int o = tid; o < NSPK; o += 512)
            out[(size_t)(t0 + t) * NSPK + o] = lg[t * NSPK + o] - lse;
        __syncthreads();
    }
}

// ---------------- launch ----------------
extern "C" void kernel_launch(void* const* d_in, const int* in_sizes, int n_in,
                              void* d_out, int out_size)
{
    const float* x    = (const float*)d_in[0];
    const float* wih0 = (const float*)d_in[1];
    const float* whh0 = (const float*)d_in[2];
    const float* bih0 = (const float*)d_in[3];
    const float* bhh0 = (const float*)d_in[4];
    const float* wih1 = (const float*)d_in[5];
    const float* whh1 = (const float*)d_in[6];
    const float* bih1 = (const float*)d_in[7];
    const float* bhh1 = (const float*)d_in[8];
    const float* wih2 = (const float*)d_in[9];
    const float* whh2 = (const float*)d_in[10];
    const float* bih2 = (const float*)d_in[11];
    const float* bhh2 = (const float*)d_in[12];
    const float* wlin = (const float*)d_in[13];
    const float* blin = (const float*)d_in[14];
    float* out = (float*)d_out;

    init_flags_kernel<<<96, 512>>>();
    lstm_pipeline_kernel<<<72, 512>>>(x,
        wih0, whh0, bih0, bhh0,
        wih1, whh1, bih1, bhh1,
        wih2, whh2, bih2, bhh2);
    classifier_kernel<<<256, 512>>>(wlin, blin, out);
}

// round 3
// speedup vs baseline: 1.1933x; 1.1933x over previous
#include <cuda_runtime.h>
#include <math.h>
#include <stdint.h>

#define T_STEPS 1024
#define HID     256
#define NSPK    1251
#define F_IN    40

// ---------------- device scratch ----------------
__device__ float g_h [3][T_STEPS][HID];  // per-layer hidden outputs (inter-layer + classifier)
__device__ int   g_fh[3][T_STEPS][16];   // per-(layer,t,cta) publish flags

// ---------------- helpers ----------------
__device__ __forceinline__ int ld_acq(const int* p) {
    int v; asm volatile("ld.global.acquire.gpu.b32 %0, [%1];" : "=r"(v) : "l"(p)); return v;
}
__device__ __forceinline__ void st_rel(int* p, int v) {
    asm volatile("st.global.release.gpu.b32 [%0], %1;" :: "l"(p), "r"(v));
}
__device__ __forceinline__ uint32_t smem_u32(const void* p) {
    uint32_t a;
    asm("{ .reg .u64 t; cvta.to.shared.u64 t, %1; cvt.u32.u64 %0, t; }" : "=r"(a) : "l"(p));
    return a;
}
__device__ __forceinline__ uint32_t mapa_u32(uint32_t addr, uint32_t rank) {
    uint32_t r; asm("mapa.shared::cluster.u32 %0, %1, %2;" : "=r"(r) : "r"(addr), "r"(rank));
    return r;
}
__device__ __forceinline__ void ffma2(unsigned long long& acc,
                                      unsigned long long a, unsigned long long b) {
    asm("fma.rn.f32x2 %0, %1, %2, %0;" : "+l"(acc) : "l"(a), "l"(b));
}
__device__ __forceinline__ unsigned long long pack2(float a, float b) {
    unsigned long long v;
    asm("mov.b64 %0, {%1,%2};" : "=l"(v) : "f"(a), "f"(b));
    return v;
}
__device__ __forceinline__ float sigf(float x) { return 1.0f / (1.0f + __expf(-x)); }

__device__ __forceinline__ void mbar_wait_parity(uint32_t mbar, uint32_t parity) {
    asm volatile(
        "{\n\t.reg .pred P;\n\t"
        "LAB_WAIT_%=:\n\t"
        "mbarrier.try_wait.parity.acquire.cluster.shared::cta.b64 P, [%0], %1, 0x989680;\n\t"
        "@P bra.uni LAB_DONE_%=;\n\t"
        "bra.uni LAB_WAIT_%=;\n\t"
        "LAB_DONE_%=:\n\t}"
        :: "r"(mbar), "r"(parity) : "memory");
}

// ---------------- init: zero publish flags ----------------
__global__ void init_flags_kernel() {
    int i = blockIdx.x * blockDim.x + threadIdx.x;
    int* f = &g_fh[0][0][0];             // 3*1024*16 = 49152
    if (i < 49152) f[i] = 0;
}

// ---------------- pipelined 3-layer LSTM, one 16-CTA cluster per layer ----------------
// grid = 48 CTAs x 512 threads, cluster dims (16,1,1):
//   cluster 0 -> layer 0, cluster 1 -> layer 1, cluster 2 -> layer 2.
// Each CTA owns 16 hidden units (64 gate rows). W_hh and W_ih slices live in
// registers as f32x2 pairs. Per step: cluster-wide h exchange via DSMEM +
// mbarrier; inter-layer handoff via global memory + release/acquire flag.
extern "C" __global__ void __launch_bounds__(512, 1)
lstm_pipeline_kernel(
    const float* __restrict__ x,
    const float* __restrict__ wih0, const float* __restrict__ whh0,
    const float* __restrict__ bih0, const float* __restrict__ bhh0,
    const float* __restrict__ wih1, const float* __restrict__ whh1,
    const float* __restrict__ bih1, const float* __restrict__ bhh1,
    const float* __restrict__ wih2, const float* __restrict__ whh2,
    const float* __restrict__ bih2, const float* __restrict__ bhh2)
{
    __shared__ float h_s[2][HID];        // parity double-buffered cluster h
    __shared__ float hp_s[HID];          // previous-layer h (l>0)
    __shared__ float x_s[F_IN];          // x[63,t,:] (l==0)
    __shared__ float gbuf[64];           // row sums
    __shared__ float h_stage[16];        // this CTA's 16 new h values
    __shared__ __align__(8) unsigned long long mbar_sto;

    const int tid = threadIdx.x;
    const int l   = blockIdx.x >> 4;
    uint32_t c;
    asm("mov.u32 %0, %%cluster_ctarank;" : "=r"(c));

    const int r    = tid >> 3;           // 0..63: gate row within CTA
    const int kc   = tid & 7;            // 0..7 : k-chunk lane
    const int gate = r >> 4, ul = r & 15;
    const int grow = gate * 256 + (int)c * 16 + ul;  // global gate row

    const float* whh = (l == 0) ? whh0 : (l == 1) ? whh1 : whh2;
    const float* wih = (l == 0) ? wih0 : (l == 1) ? wih1 : wih2;
    const float* bih = (l == 0) ? bih0 : (l == 1) ? bih1 : bih2;
    const float* bhh = (l == 0) ? bhh0 : (l == 1) ? bhh1 : bhh2;

    // W_hh slice: quads q cover floats [32q+4kc, 32q+4kc+4) -> bank-conflict-free LDS.128
    unsigned long long wh[16];
    #pragma unroll
    for (int q = 0; q < 8; q++) {
        const float* pr = whh + grow * HID + 32 * q + 4 * kc;
        wh[2*q]   = *(const unsigned long long*)(pr);
        wh[2*q+1] = *(const unsigned long long*)(pr + 2);
    }
    unsigned long long wi[16];
    float wx[5];
    if (l == 0) {
        #pragma unroll
        for (int j = 0; j < 5; j++) wx[j] = wih[grow * F_IN + kc * 5 + j];
    } else {
        #pragma unroll
        for (int q = 0; q < 8; q++) {
            const float* pr = wih + grow * HID + 32 * q + 4 * kc;
            wi[2*q]   = *(const unsigned long long*)(pr);
            wi[2*q+1] = *(const unsigned long long*)(pr + 2);
        }
    }
    const float brow = bih[grow] + bhh[grow];   // consumed by kc==0 lane

    const uint32_t mbar = smem_u32(&mbar_sto);
    if (tid == 0) {
        asm volatile("mbarrier.init.shared.b64 [%0], 16;" :: "r"(mbar) : "memory");
    }
    if (tid < HID) h_s[0][tid] = 0.0f;

    // Precompute remote DSMEM addresses.
    // Push threads: tid<128 -> (rank rk = tid&15, pair q2 = tid>>4 in [0,8))
    uint32_t ra0 = 0, ra1 = 0, rbar = 0;
    if (tid < 128) {
        int rk = tid & 15, q2 = tid >> 4;
        ra0 = mapa_u32(smem_u32(&h_s[0][(int)c * 16 + 2 * q2]), (uint32_t)rk);
        ra1 = mapa_u32(smem_u32(&h_s[1][(int)c * 16 + 2 * q2]), (uint32_t)rk);
    }
    if (tid < 16) rbar = mapa_u32(mbar, (uint32_t)tid);

    __syncthreads();
    asm volatile("barrier.cluster.arrive.aligned;" ::: "memory");
    asm volatile("barrier.cluster.wait.aligned;"   ::: "memory");

    float xr = 0.0f;
    if (l == 0 && tid < F_IN) xr = x[(63 * T_STEPS + 0) * F_IN + tid];

    float cst = 0.0f;

    for (int t = 0; t < T_STEPS; t++) {
        const int rb = t & 1;            // read-buffer parity

        if (l > 0) {
            // fetch h_{l-1}[t] from global (flag set by upstream cluster)
            if (tid < 16) { while (ld_acq(&g_fh[l-1][t][tid]) == 0) {} }
            __syncthreads();
            if (tid < 64) {
                float4 v = *(const float4*)&g_h[l-1][t][tid * 4];
                *(float4*)&hp_s[tid * 4] = v;
            }
            if (t > 0) mbar_wait_parity(mbar, (t - 1) & 1);
            __syncthreads();
        } else {
            if (tid < F_IN) x_s[tid] = xr;
            if (t > 0) mbar_wait_parity(mbar, (t - 1) & 1);
            __syncthreads();
            if (tid < F_IN && t + 1 < T_STEPS)
                xr = x[(63 * T_STEPS + (t + 1)) * F_IN + tid];  // prefetch
        }

        // ---- matvec: this thread's 32-wide k slice (skewed quads) ----
        unsigned long long acc = 0ULL;
        {
            const float* hb = &h_s[rb][4 * kc];
            #pragma unroll
            for (int q = 0; q < 8; q++) {
                float4 hv = *(const float4*)(hb + 32 * q);
                ffma2(acc, wh[2*q],   pack2(hv.x, hv.y));
                ffma2(acc, wh[2*q+1], pack2(hv.z, hv.w));
            }
        }
        float px = 0.0f;
        if (l > 0) {
            const float* pb = &hp_s[4 * kc];
            #pragma unroll
            for (int q = 0; q < 8; q++) {
                float4 hv = *(const float4*)(pb + 32 * q);
                ffma2(acc, wi[2*q],   pack2(hv.x, hv.y));
                ffma2(acc, wi[2*q+1], pack2(hv.z, hv.w));
            }
        } else {
            #pragma unroll
            for (int j = 0; j < 5; j++) px = fmaf(wx[j], x_s[kc * 5 + j], px);
        }
        float lo, hi;
        asm("mov.b64 {%0,%1}, %2;" : "=f"(lo), "=f"(hi) : "l"(acc));
        float p = lo + hi + px;

        // in-warp reduce over the 8 kc lanes of each row
        p += __shfl_xor_sync(0xffffffffu, p, 1);
        p += __shfl_xor_sync(0xffffffffu, p, 2);
        p += __shfl_xor_sync(0xffffffffu, p, 4);
        if (kc == 0) gbuf[r] = p + brow;
        __syncthreads();

        // ---- gates (16 threads, one per hidden unit) ----
        if (tid < 16) {
            float gi = gbuf[tid], gf = gbuf[16 + tid];
            float gc = gbuf[32 + tid], go = gbuf[48 + tid];
            float ii = sigf(gi), ff = sigf(gf);
            float cc = tanhf(gc), oo = sigf(go);
            cst = ff * cst + ii * cc;
            h_stage[tid] = oo * tanhf(cst);
        }
        __syncthreads();

        // ---- cluster push: write h(t) into every rank's h_s[rb^1] ----
        if (tid < 128) {
            int q2 = tid >> 4;
            unsigned long long v = pack2(h_stage[2 * q2], h_stage[2 * q2 + 1]);
            uint32_t ra = rb ? ra0 : ra1;
            asm volatile("st.shared::cluster.b64 [%0], %1;" :: "r"(ra), "l"(v) : "memory");
        }
        // ---- global publish for next layer / classifier ----
        if (tid >= 256 && tid < 272) {
            g_h[l][t][(int)c * 16 + (tid - 256)] = h_stage[tid - 256];
            __syncwarp(0x0000FFFFu);
            if (tid == 256) st_rel(&g_fh[l][t][c], 1);
        }
        __syncthreads();
        if (tid < 16) {
            asm volatile("mbarrier.arrive.release.cluster.shared::cluster.b64 _, [%0];"
                         :: "r"(rbar) : "memory");
        }
    }

    asm volatile("barrier.cluster.arrive.aligned;" ::: "memory");
    asm volatile("barrier.cluster.wait.aligned;"   ::: "memory");
}

// ---------------- classifier: logits = h2 @ W_lin^T + b, log_softmax ----------------
__global__ __launch_bounds__(512, 1) void classifier_kernel(
    const float* __restrict__ wlin,
    const float* __restrict__ blin,
    float* __restrict__ out)
{
    __shared__ float lg[4 * NSPK];
    __shared__ float hsm[4 * HID];
    __shared__ float rbuf[16];

    const int b    = blockIdx.x;
    const int t0   = b * 4;
    const int tid  = threadIdx.x;
    const int lane = tid & 31;
    const int wd   = tid >> 5;

    for (int i = tid; i < 4 * HID; i += 512)
        hsm[i] = g_h[2][t0 + (i >> 8)][i & 255];
    __syncthreads();

    float hr[4][8];
    #pragma unroll
    for (int t = 0; t < 4; t++)
        #pragma unroll
        for (int j = 0; j < 8; j++) hr[t][j] = hsm[t * HID + lane * 8 + j];

    for (int o = wd; o < NSPK; o += 16) {
        const float4* wp = (const float4*)(wlin + o * HID + lane * 8);
        float4 w0 = wp[0], w1 = wp[1];
        float wv[8] = {w0.x, w0.y, w0.z, w0.w, w1.x, w1.y, w1.z, w1.w};
        float a0 = 0.f, a1 = 0.f, a2 = 0.f, a3 = 0.f;
        #pragma unroll
        for (int j = 0; j < 8; j++) {
            float wj = wv[j];
            a0 = fmaf(wj, hr[0][j], a0);
            a1 = fmaf(wj, hr[1][j], a1);
            a2 = fmaf(wj, hr[2][j], a2);
            a3 = fmaf(wj, hr[3][j], a3);
        }
        #pragma unroll
        for (int off = 16; off > 0; off >>= 1) {
            a0 += __shfl_xor_sync(0xffffffffu, a0, off);
            a1 += __shfl_xor_sync(0xffffffffu, a1, off);
            a2 += __shfl_xor_sync(0xffffffffu, a2, off);
            a3 += __shfl_xor_sync(0xffffffffu, a3, off);
        }
        if (lane == 0) {
            float bb = blin[o];
            lg[0 * NSPK + o] = a0 + bb;
            lg[1 * NSPK + o] = a1 + bb;
            lg[2 * NSPK + o] = a2 + bb;
            lg[3 * NSPK + o] = a3 + bb;
        }
    }
    __syncthreads();

    for (int t = 0; t < 4; t++) {
        float m = -1e30f;
        for (int o = tid; o < NSPK; o += 512) m = fmaxf(m, lg[t * NSPK + o]);
        #pragma unroll
        for (int off = 16; off > 0; off >>= 1)
            m = fmaxf(m, __shfl_xor_sync(0xffffffffu, m, off));
        if (lane == 0) rbuf[wd] = m;
        __syncthreads();
        float mm = rbuf[0];
        #pragma unroll
        for (int i = 1; i < 16; i++) mm = fmaxf(mm, rbuf[i]);
        __syncthreads();

        float s = 0.0f;
        for (int o = tid; o < NSPK; o += 512) s += __expf(lg[t * NSPK + o] - mm);
        #pragma unroll
        for (int off = 16; off > 0; off >>= 1)
            s += __shfl_xor_sync(0xffffffffu, s, off);
        if (lane == 0) rbuf[wd] = s;
        __syncthreads();
        float ss = 0.0f;
        #pragma unroll
        for (int i = 0; i < 16; i++) ss += rbuf[i];
        float lse = mm + logf(ss);

        for (int o = tid; o < NSPK; o += 512)
            out[(size_t)(t0 + t) * NSPK + o] = lg[t * NSPK + o] - lse;
        __syncthreads();
    }
}

// ---------------- launch ----------------
extern "C" void kernel_launch(void* const* d_in, const int* in_sizes, int n_in,
                              void* d_out, int out_size)
{
    const float* x    = (const float*)d_in[0];
    const float* wih0 = (const float*)d_in[1];
    const float* whh0 = (const float*)d_in[2];
    const float* bih0 = (const float*)d_in[3];
    const float* bhh0 = (const float*)d_in[4];
    const float* wih1 = (const float*)d_in[5];
    const float* whh1 = (const float*)d_in[6];
    const float* bih1 = (const float*)d_in[7];
    const float* bhh1 = (const float*)d_in[8];
    const float* wih2 = (const float*)d_in[9];
    const float* whh2 = (const float*)d_in[10];
    const float* bih2 = (const float*)d_in[11];
    const float* bhh2 = (const float*)d_in[12];
    const float* wlin = (const float*)d_in[13];
    const float* blin = (const float*)d_in[14];
    float* out = (float*)d_out;

    init_flags_kernel<<<96, 512>>>();

    cudaFuncSetAttribute(lstm_pipeline_kernel,
                         cudaFuncAttributeNonPortableClusterSizeAllowed, 1);

    cudaLaunchConfig_t cfg = {};
    cfg.gridDim  = dim3(48, 1, 1);
    cfg.blockDim = dim3(512, 1, 1);
    cfg.dynamicSmemBytes = 0;
    cfg.stream = 0;
    cudaLaunchAttribute attrs[1];
    attrs[0].id = cudaLaunchAttributeClusterDimension;
    attrs[0].val.clusterDim.x = 16;
    attrs[0].val.clusterDim.y = 1;
    attrs[0].val.clusterDim.z = 1;
    cfg.attrs = attrs;
    cfg.numAttrs = 1;

    cudaLaunchKernelEx(&cfg, lstm_pipeline_kernel, x,
                       wih0, whh0, bih0, bhh0,
                       wih1, whh1, bih1, bhh1,
                       wih2, whh2, bih2, bhh2);

    classifier_kernel<<<256, 512>>>(wlin, blin, out);
}

// round 7
// speedup vs baseline: 1.2279x; 1.0291x over previous
#include <cuda_runtime.h>
#include <math.h>
#include <stdint.h>

#define T_STEPS 1024
#define HID     256
#define NSPK    1251
#define F_IN    40

// ---------------- device scratch ----------------
__device__ float g_h [3][T_STEPS][HID];  // per-layer hidden outputs
__device__ int   g_fh[3][T_STEPS][16];   // per-(layer,t,cta) publish flags

// ---------------- helpers ----------------
__device__ __forceinline__ int ld_acq(const int* p) {
    int v; asm volatile("ld.global.acquire.gpu.b32 %0, [%1];" : "=r"(v) : "l"(p)); return v;
}
__device__ __forceinline__ void st_rel(int* p, int v) {
    asm volatile("st.global.release.gpu.b32 [%0], %1;" :: "l"(p), "r"(v));
}
__device__ __forceinline__ void ffma2(unsigned long long& acc,
                                      unsigned long long a, unsigned long long b) {
    asm("fma.rn.f32x2 %0, %1, %2, %0;" : "+l"(acc) : "l"(a), "l"(b));
}
__device__ __forceinline__ unsigned long long pack2(float a, float b) {
    unsigned long long v;
    asm("mov.b64 %0, {%1,%2};" : "=l"(v) : "f"(a), "f"(b));
    return v;
}
__device__ __forceinline__ float sigf(float x) { return 1.0f / (1.0f + __expf(-x)); }
__device__ __forceinline__ float tanh_fast(float x) {
    return 2.0f / (1.0f + __expf(-2.0f * x)) - 1.0f;
}

// ---------------- init: zero publish flags ----------------
__global__ void init_flags_kernel() {
    int i = blockIdx.x * blockDim.x + threadIdx.x;
    int* f = &g_fh[0][0][0];             // 3*1024*16 = 49152
    if (i < 49152) f[i] = 0;
}

// ---------------- pipelined 3-layer LSTM (no clusters) ----------------
// grid = 48 CTAs x 512 threads. CTA (l, c): layer l = bid>>4, c = bid&15 owns
// hidden units [16c, 16c+16) -> 64 gate rows. W_hh AND W_ih slices live in
// registers (f32x2). Exchange via global h + release/acquire flags:
//   warp0 lanes 0-15 : poll+load own-layer h[t-1], also compute gates + publish
//   warp1 lanes 0-15 : poll+load upstream h[t]        (l>0)
//   warp1+2          : stage x[63,t] into smem        (l==0)
extern "C" __global__ void __launch_bounds__(512, 1)
lstm_pipeline_kernel(
    const float* __restrict__ x,
    const float* __restrict__ wih0, const float* __restrict__ whh0,
    const float* __restrict__ bih0, const float* __restrict__ bhh0,
    const float* __restrict__ wih1, const float* __restrict__ whh1,
    const float* __restrict__ bih1, const float* __restrict__ bhh1,
    const float* __restrict__ wih2, const float* __restrict__ whh2,
    const float* __restrict__ bih2, const float* __restrict__ bhh2)
{
    __shared__ float h_s[HID];           // own layer h(t-1)
    __shared__ float hp_s[HID];          // upstream layer h(t)   (l>0)
    __shared__ float x_s[F_IN];          // x[63,t,:]             (l==0)
    __shared__ float gbuf[64];           // per-gate-row sums

    const int tid = threadIdx.x;
    const int l   = blockIdx.x >> 4;
    const int c   = blockIdx.x & 15;

    const int r    = tid >> 3;           // 0..63 : gate row within CTA
    const int kc   = tid & 7;            // 0..7  : k-chunk lane
    const int gate = r >> 4, ul = r & 15;
    const int grow = gate * 256 + c * 16 + ul;       // global gate row

    const float* whh = (l == 0) ? whh0 : (l == 1) ? whh1 : whh2;
    const float* wih = (l == 0) ? wih0 : (l == 1) ? wih1 : wih2;
    const float* bih = (l == 0) ? bih0 : (l == 1) ? bih1 : bih2;
    const float* bhh = (l == 0) ? bhh0 : (l == 1) ? bhh1 : bhh2;

    // W_hh slice: quad q covers floats [32q+4kc, 32q+4kc+4) -> conflict-free LDS.128
    unsigned long long wh[16];
    #pragma unroll
    for (int q = 0; q < 8; q++) {
        const float* pr = whh + grow * HID + 32 * q + 4 * kc;
        wh[2*q]   = *(const unsigned long long*)(pr);
        wh[2*q+1] = *(const unsigned long long*)(pr + 2);
    }
    unsigned long long wi[16];
    float wx[5];
    if (l == 0) {
        #pragma unroll
        for (int j = 0; j < 5; j++) wx[j] = wih[grow * F_IN + kc * 5 + j];
    } else {
        #pragma unroll
        for (int q = 0; q < 8; q++) {
            const float* pr = wih + grow * HID + 32 * q + 4 * kc;
            wi[2*q]   = *(const unsigned long long*)(pr);
            wi[2*q+1] = *(const unsigned long long*)(pr + 2);
        }
    }
    const float brow = bih[grow] + bhh[grow];        // used by kc==0 lane

    // zero h(-1)
    if (tid < 64) *(float4*)&h_s[tid * 4] = make_float4(0.f, 0.f, 0.f, 0.f);

    float xr = 0.0f;
    if (l == 0 && tid >= 32 && tid < 32 + F_IN)
        xr = x[(63 * T_STEPS + 0) * F_IN + (tid - 32)];

    float cst = 0.0f;                    // cell state (tid<16)
    __syncthreads();

    for (int t = 0; t < T_STEPS; t++) {
        // ---- fused poll + load (warp0: own layer; warp1: upstream / x) ----
        if (tid < 16) {
            if (t > 0) {
                while (ld_acq(&g_fh[l][t-1][tid]) == 0) {}
                const float4* src = (const float4*)&g_h[l][t-1][tid * 16];
                float4 a = src[0], b = src[1], d = src[2], e = src[3];
                float4* dst = (float4*)&h_s[tid * 16];
                dst[0] = a; dst[1] = b; dst[2] = d; dst[3] = e;
            }
        } else if (l > 0) {
            if (tid >= 32 && tid < 48) {
                const int j = tid - 32;
                while (ld_acq(&g_fh[l-1][t][j]) == 0) {}
                const float4* src = (const float4*)&g_h[l-1][t][j * 16];
                float4 a = src[0], b = src[1], d = src[2], e = src[3];
                float4* dst = (float4*)&hp_s[j * 16];
                dst[0] = a; dst[1] = b; dst[2] = d; dst[3] = e;
            }
        } else {
            if (tid >= 32 && tid < 32 + F_IN) {
                x_s[tid - 32] = xr;
                if (t + 1 < T_STEPS)
                    xr = x[(63 * T_STEPS + (t + 1)) * F_IN + (tid - 32)];
            }
        }
        __syncthreads();

        // ---- matvec: 32-wide k-slice, packed f32x2 FMAs ----
        unsigned long long acc = 0ULL;
        {
            const float* hb = &h_s[4 * kc];
            #pragma unroll
            for (int q = 0; q < 8; q++) {
                float4 hv = *(const float4*)(hb + 32 * q);
                ffma2(acc, wh[2*q],   pack2(hv.x, hv.y));
                ffma2(acc, wh[2*q+1], pack2(hv.z, hv.w));
            }
        }
        float px = 0.0f;
        if (l > 0) {
            const float* pb = &hp_s[4 * kc];
            #pragma unroll
            for (int q = 0; q < 8; q++) {
                float4 hv = *(const float4*)(pb + 32 * q);
                ffma2(acc, wi[2*q],   pack2(hv.x, hv.y));
                ffma2(acc, wi[2*q+1], pack2(hv.z, hv.w));
            }
        } else {
            #pragma unroll
            for (int j = 0; j < 5; j++) px = fmaf(wx[j], x_s[kc * 5 + j], px);
        }
        float lo, hi;
        asm("mov.b64 {%0,%1}, %2;" : "=f"(lo), "=f"(hi) : "l"(acc));
        float p = lo + hi + px;

        p += __shfl_xor_sync(0xffffffffu, p, 1);
        p += __shfl_xor_sync(0xffffffffu, p, 2);
        p += __shfl_xor_sync(0xffffffffu, p, 4);
        if (kc == 0) gbuf[r] = p + brow;
        __syncthreads();

        // ---- gates + publish (warp0 lanes 0-15) ----
        if (tid < 16) {
            float gi = gbuf[tid],      gf = gbuf[16 + tid];
            float gc = gbuf[32 + tid], go = gbuf[48 + tid];
            float ii = sigf(gi), ff = sigf(gf);
            float cc = tanh_fast(gc), oo = sigf(go);
            cst = ff * cst + ii * cc;
            float hn = oo * tanh_fast(cst);

            // pack 4 lanes -> float4 via shuffles, lanes {0,4,8,12} store
            const int base = tid & 12;
            float a0 = __shfl_sync(0x0000FFFFu, hn, base + 0);
            float a1 = __shfl_sync(0x0000FFFFu, hn, base + 1);
            float a2 = __shfl_sync(0x0000FFFFu, hn, base + 2);
            float a3 = __shfl_sync(0x0000FFFFu, hn, base + 3);
            if ((tid & 3) == 0) {
                float4 v = make_float4(a0, a1, a2, a3);
                *(float4*)&g_h[l][t][c * 16 + base] = v;
            }
            __syncwarp(0x0000FFFFu);
            if (tid == 0) st_rel(&g_fh[l][t][c], 1);
        }
    }
}

// ---------------- classifier: logits = h2 @ W_lin^T + b, log_softmax ----------------
__global__ __launch_bounds__(512, 1) void classifier_kernel(
    const float* __restrict__ wlin,
    const float* __restrict__ blin,
    float* __restrict__ out)
{
    __shared__ float lg[4 * NSPK];
    __shared__ float hsm[4 * HID];
    __shared__ float rbuf[16];

    const int b    = blockIdx.x;
    const int t0   = b * 4;
    const int tid  = threadIdx.x;
    const int lane = tid & 31;
    const int wd   = tid >> 5;

    for (int i = tid; i < 4 * HID; i += 512)
        hsm[i] = g_h[2][t0 + (i >> 8)][i & 255];
    __syncthreads();

    float hr[4][8];
    #pragma unroll
    for (int t = 0; t < 4; t++)
        #pragma unroll
        for (int j = 0; j < 8; j++) hr[t][j] = hsm[t * HID + lane * 8 + j];

    for (int o = wd; o < NSPK; o += 16) {
        const float4* wp = (const float4*)(wlin + o * HID + lane * 8);
        float4 w0 = wp[0], w1 = wp[1];
        float wv[8] = {w0.x, w0.y, w0.z, w0.w, w1.x, w1.y, w1.z, w1.w};
        float a0 = 0.f, a1 = 0.f, a2 = 0.f, a3 = 0.f;
        #pragma unroll
        for (int j = 0; j < 8; j++) {
            float wj = wv[j];
            a0 = fmaf(wj, hr[0][j], a0);
            a1 = fmaf(wj, hr[1][j], a1);
            a2 = fmaf(wj, hr[2][j], a2);
            a3 = fmaf(wj, hr[3][j], a3);
        }
        #pragma unroll
        for (int off = 16; off > 0; off >>= 1) {
            a0 += __shfl_xor_sync(0xffffffffu, a0, off);
            a1 += __shfl_xor_sync(0xffffffffu, a1, off);
            a2 += __shfl_xor_sync(0xffffffffu, a2, off);
            a3 += __shfl_xor_sync(0xffffffffu, a3, off);
        }
        if (lane == 0) {
            float bb = blin[o];
            lg[0 * NSPK + o] = a0 + bb;
            lg[1 * NSPK + o] = a1 + bb;
            lg[2 * NSPK + o] = a2 + bb;
            lg[3 * NSPK + o] = a3 + bb;
        }
    }
    __syncthreads();

    for (int t = 0; t < 4; t++) {
        float m = -1e30f;
        for (int o = tid; o < NSPK; o += 512) m = fmaxf(m, lg[t * NSPK + o]);
        #pragma unroll
        for (int off = 16; off > 0; off >>= 1)
            m = fmaxf(m, __shfl_xor_sync(0xffffffffu, m, off));
        if (lane == 0) rbuf[wd] = m;
        __syncthreads();
        float mm = rbuf[0];
        #pragma unroll
        for (int i = 1; i < 16; i++) mm = fmaxf(mm, rbuf[i]);
        __syncthreads();

        float s = 0.0f;
        for (int o = tid; o < NSPK; o += 512) s += __expf(lg[t * NSPK + o] - mm);
        #pragma unroll
        for (int off = 16; off > 0; off >>= 1)
            s += __shfl_xor_sync(0xffffffffu, s, off);
        if (lane == 0) rbuf[wd] = s;
        __syncthreads();
        float ss = 0.0f;
        #pragma unroll
        for (int i = 0; i < 16; i++) ss += rbuf[i];
        float lse = mm + logf(ss);

        for (int o = tid; o < NSPK; o += 512)
            out[(size_t)(t0 + t) * NSPK + o] = lg[t * NSPK + o] - lse;
        __syncthreads();
    }
}

// ---------------- launch ----------------
extern "C" void kernel_launch(void* const* d_in, const int* in_sizes, int n_in,
                              void* d_out, int out_size)
{
    const float* x    = (const float*)d_in[0];
    const float* wih0 = (const float*)d_in[1];
    const float* whh0 = (const float*)d_in[2];
    const float* bih0 = (const float*)d_in[3];
    const float* bhh0 = (const float*)d_in[4];
    const float* wih1 = (const float*)d_in[5];
    const float* whh1 = (const float*)d_in[6];
    const float* bih1 = (const float*)d_in[7];
    const float* bhh1 = (const float*)d_in[8];
    const float* wih2 = (const float*)d_in[9];
    const float* whh2 = (const float*)d_in[10];
    const float* bih2 = (const float*)d_in[11];
    const float* bhh2 = (const float*)d_in[12];
    const float* wlin = (const float*)d_in[13];
    const float* blin = (const float*)d_in[14];
    float* out = (float*)d_out;

    init_flags_kernel<<<96, 512>>>();
    lstm_pipeline_kernel<<<48, 512>>>(x,
        wih0, whh0, bih0, bhh0,
        wih1, whh1, bih1, bhh1,
        wih2, whh2, bih2, bhh2);
    classifier_kernel<<<256, 512>>>(wlin, blin, out);
}